// round 11
// baseline (speedup 1.0000x reference)
#include <cuda_runtime.h>
#include <cstdint>

// Problem constants (fixed by setup_inputs): frames=64, height=23, width=24,
// hidden=1152, interval=1.
constexpr int FRAMES = 64;
constexpr int H      = 23;
constexpr int W      = 24;
constexpr int HIDDEN = 1152;
constexpr int TPF    = H * W;              // 552
constexpr int TOTAL  = FRAMES * TPF;       // 35328
constexpr int VALID  = (FRAMES - 1) * TPF; // 34776 tokens with a valid next frame
constexpr int OFF_R  = TPF + 1;            // +553 flat: right neighbor in next frame
constexpr int OFF_D  = TPF + W;            // +576 flat: down neighbor in next frame
constexpr float EPS  = 1e-8f;

// Tiling: block owns B contiguous tokens; neighbor span [p0+553, p0+B+576) is
// B+23 contiguous vectors, each used TWICE (right for token u-553, down for
// token u-576) -> stage once in smem. L2 amplification drops 3x -> 2.09x.
constexpr int B         = 128;             // tokens per block
constexpr int SPAN_USED = B + 23;          // 151 staged vectors
constexpr int SPAN      = B + 24;          // padded
constexpr int CH        = 128;             // floats per hidden chunk (512 B)
constexpr int NCH       = HIDDEN / CH;     // 9
constexpr int THREADS   = 512;             // 16 warps
constexpr int NWARP     = THREADS / 32;
constexpr int TPW       = B / NWARP;       // 8 tokens per warp
constexpr int SMEM_BYTES = 2 * SPAN * CH * 4;  // 155648 B (double buffer)

__device__ __forceinline__ void cp_async16(uint32_t dst, const void* src) {
    asm volatile("cp.async.cg.shared.global [%0], [%1], 16;" :: "r"(dst), "l"(src));
}
__device__ __forceinline__ void cp_commit() {
    asm volatile("cp.async.commit_group;");
}

__global__ void __launch_bounds__(THREADS, 1)
simdiff_tiled(const float* __restrict__ x,
              float* __restrict__ out_right,
              float* __restrict__ out_down) {
    extern __shared__ float smem[];
    const int tid  = threadIdx.x;
    const int warp = tid >> 5;
    const int lane = tid & 31;
    const int p0   = blockIdx.x * B;

    uint32_t smem_u32;
    asm("{ .reg .u64 t; cvta.to.shared.u64 t, %1; cvt.u32.u64 %0, t; }"
        : "=r"(smem_u32) : "l"(smem));

    // Stage chunk ch of the neighbor span into buffer `buf`.
    auto stage = [&](int buf, int ch) {
        const uint32_t sbase = smem_u32 + (uint32_t)buf * SPAN * CH * 4;
        for (int p = tid; p < SPAN_USED * 32; p += THREADS) {
            const int v = p >> 5;
            const int q = p & 31;
            int u = p0 + OFF_R + v;
            if (u > TOTAL - 1) u = TOTAL - 1;   // clamp (garbage discarded)
            const float* src = x + (size_t)u * HIDDEN + ch * CH + q * 4;
            cp_async16(sbase + (uint32_t)(v * CH + q * 4) * 4, src);
        }
    };

    float na[TPW], dr[TPW], nr[TPW], dd[TPW], nd[TPW];
#pragma unroll
    for (int k = 0; k < TPW; k++) { na[k]=0.f; dr[k]=0.f; nr[k]=0.f; dd[k]=0.f; nd[k]=0.f; }

    stage(0, 0);
    cp_commit();

    for (int ch = 0; ch < NCH; ch++) {
        if (ch + 1 < NCH) {
            stage((ch + 1) & 1, ch + 1);
            cp_commit();
            asm volatile("cp.async.wait_group 1;");
        } else {
            asm volatile("cp.async.wait_group 0;");
        }
        __syncthreads();

        const float* bufp = smem + (ch & 1) * SPAN * CH;
#pragma unroll
        for (int k = 0; k < TPW; k++) {
            const int tk = warp * TPW + k;
            const int t  = p0 + tk;
            if (t >= VALID) continue;   // uniform per warp-iteration
            // a read straight from gmem (1x traffic), streaming hint.
            float4 a = __ldcs((const float4*)(x + (size_t)t * HIDDEN + ch * CH + lane * 4));
            float4 r = *(const float4*)(bufp + tk * CH + lane * 4);           // t+553
            float4 d = *(const float4*)(bufp + (tk + (OFF_D - OFF_R)) * CH + lane * 4); // t+576
            na[k] = fmaf(a.x, a.x, na[k]);
            na[k] = fmaf(a.y, a.y, na[k]);
            na[k] = fmaf(a.z, a.z, na[k]);
            na[k] = fmaf(a.w, a.w, na[k]);
            dr[k] = fmaf(a.x, r.x, dr[k]);
            dr[k] = fmaf(a.y, r.y, dr[k]);
            dr[k] = fmaf(a.z, r.z, dr[k]);
            dr[k] = fmaf(a.w, r.w, dr[k]);
            nr[k] = fmaf(r.x, r.x, nr[k]);
            nr[k] = fmaf(r.y, r.y, nr[k]);
            nr[k] = fmaf(r.z, r.z, nr[k]);
            nr[k] = fmaf(r.w, r.w, nr[k]);
            dd[k] = fmaf(a.x, d.x, dd[k]);
            dd[k] = fmaf(a.y, d.y, dd[k]);
            dd[k] = fmaf(a.z, d.z, dd[k]);
            dd[k] = fmaf(a.w, d.w, dd[k]);
            nd[k] = fmaf(d.x, d.x, nd[k]);
            nd[k] = fmaf(d.y, d.y, nd[k]);
            nd[k] = fmaf(d.z, d.z, nd[k]);
            nd[k] = fmaf(d.w, d.w, nd[k]);
        }
        __syncthreads();
    }

    // Per-token warp reductions + writes.
#pragma unroll
    for (int k = 0; k < TPW; k++) {
        const int t = p0 + warp * TPW + k;
        if (t >= VALID) continue;
        float s_na = na[k], s_dr = dr[k], s_nr = nr[k], s_dd = dd[k], s_nd = nd[k];
#pragma unroll
        for (int off = 16; off > 0; off >>= 1) {
            s_na += __shfl_xor_sync(0xFFFFFFFFu, s_na, off);
            s_dr += __shfl_xor_sync(0xFFFFFFFFu, s_dr, off);
            s_nr += __shfl_xor_sync(0xFFFFFFFFu, s_nr, off);
            s_dd += __shfl_xor_sync(0xFFFFFFFFu, s_dd, off);
            s_nd += __shfl_xor_sync(0xFFFFFFFFu, s_nd, off);
        }
        if (lane == 0) {
            const int i = t % TPF;
            const float norm_a = fmaxf(sqrtf(s_na), EPS);
            out_right[t] = (i < TPF - 1)
                ? s_dr / (norm_a * fmaxf(sqrtf(s_nr), EPS)) : -1.0f;
            out_down[t]  = (i < TPF - W)
                ? s_dd / (norm_a * fmaxf(sqrtf(s_nd), EPS)) : -1.0f;
        }
    }
}

// Last frame (no next frame): all outputs are -1.
__global__ void simdiff_tail(float* __restrict__ out_right,
                             float* __restrict__ out_down) {
    const int t = VALID + blockIdx.x * blockDim.x + threadIdx.x;
    if (t < TOTAL) { out_right[t] = -1.0f; out_down[t] = -1.0f; }
}

extern "C" void kernel_launch(void* const* d_in, const int* in_sizes, int n_in,
                              void* d_out, int out_size) {
    const float* x = (const float*)d_in[0];
    float* out       = (float*)d_out;
    float* out_right = out;
    float* out_down  = out + TOTAL;

    cudaFuncSetAttribute(simdiff_tiled,
                         cudaFuncAttributeMaxDynamicSharedMemorySize, SMEM_BYTES);

    const int blocks = (VALID + B - 1) / B;   // 272
    simdiff_tiled<<<blocks, THREADS, SMEM_BYTES>>>(x, out_right, out_down);

    const int tail = TOTAL - VALID;           // 552
    simdiff_tail<<<(tail + 255) / 256, 256>>>(out_right, out_down);
}

// round 12
// speedup vs baseline: 1.0315x; 1.0315x over previous
#include <cuda_runtime.h>
#include <cstdint>

// Problem constants (fixed by setup_inputs): frames=64, height=23, width=24,
// hidden=1152, interval=1.
constexpr int FRAMES = 64;
constexpr int H      = 23;
constexpr int W      = 24;
constexpr int HIDDEN = 1152;
constexpr int TPF    = H * W;              // 552
constexpr int TOTAL  = FRAMES * TPF;       // 35328
constexpr int VALID  = (FRAMES - 1) * TPF; // 34776
constexpr int OFF_R  = TPF + 1;            // +553 flat
constexpr int OFF_D  = TPF + W;            // +576 flat
constexpr float EPS  = 1e-8f;

// Block owns B contiguous tokens; within one hidden chunk the neighbor window
// (B+23 vectors x 512 B = 77 KB) fits L1, so the d-read of token t hits the
// L1 line fetched by the r-read of token t+23 (same block, same chunk).
// L2 amplification: 3x -> ~2.2x with zero staging overhead.
constexpr int B       = 128;               // tokens per block
constexpr int THREADS = 512;               // 16 warps
constexpr int NWARP   = THREADS / 32;
constexpr int TPW     = B / NWARP;         // 8 tokens per warp
constexpr int CH      = 128;               // floats per hidden chunk (512 B)
constexpr int NCH     = HIDDEN / CH;       // 9
constexpr int MAIN_BLOCKS = (VALID + B - 1) / B;  // 272
constexpr int TAIL_BLOCKS = 2;             // last-frame -1 writes
constexpr size_t ROWB = (size_t)HIDDEN * 4;  // 4608 bytes per token vector

__global__ void __launch_bounds__(THREADS, 2)
simdiff_l1(const float* __restrict__ x,
           float* __restrict__ out_right,
           float* __restrict__ out_down) {
    const int tid  = threadIdx.x;
    const int warp = tid >> 5;
    const int lane = tid & 31;

    // Tail blocks: last frame gets -1 everywhere (folded into same launch).
    if (blockIdx.x >= MAIN_BLOCKS) {
        const int t = VALID + (blockIdx.x - MAIN_BLOCKS) * THREADS + tid;
        if (t < TOTAL) { out_right[t] = -1.0f; out_down[t] = -1.0f; }
        return;
    }

    const int p0 = blockIdx.x * B;
    const int t0 = p0 + warp * TPW;

    // Per-token validity masks (computed once; reused in chunk loop + epilogue).
    unsigned am = 0, rm = 0, dm = 0;
#pragma unroll
    for (int k = 0; k < TPW; k++) {
        const int t = t0 + k;
        if (t < VALID) {
            am |= 1u << k;
            const int i = t % TPF;
            if (i < TPF - 1) rm |= 1u << k;
            if (i < TPF - W) dm |= 1u << k;
        }
    }

    float na[TPW], dr[TPW], nr[TPW], dd[TPW], nd[TPW];
#pragma unroll
    for (int k = 0; k < TPW; k++) { na[k]=0.f; dr[k]=0.f; nr[k]=0.f; dd[k]=0.f; nd[k]=0.f; }

    const char* base0 = (const char*)x + (size_t)t0 * ROWB + (size_t)lane * 16;

    for (int ch = 0; ch < NCH; ch++) {
        __syncthreads();   // keep all warps inside the same 77 KB L1 window
        const char* base = base0 + (size_t)ch * (CH * 4);
#pragma unroll
        for (int k = 0; k < TPW; k++) {
            if (am >> k & 1u) {
                const char* pa = base + (size_t)k * ROWB;
                // self vector: single use -> streaming (evict-first in L1)
                float4 a = __ldcs((const float4*)pa);
                // neighbors: cached; invalid ones clamped to self (discarded)
                const float4* pr = (rm >> k & 1u)
                    ? (const float4*)(pa + (size_t)OFF_R * ROWB) : (const float4*)pa;
                const float4* pd = (dm >> k & 1u)
                    ? (const float4*)(pa + (size_t)OFF_D * ROWB) : (const float4*)pa;
                float4 r = __ldg(pr);
                float4 d = __ldg(pd);

                na[k] = fmaf(a.x, a.x, na[k]);
                na[k] = fmaf(a.y, a.y, na[k]);
                na[k] = fmaf(a.z, a.z, na[k]);
                na[k] = fmaf(a.w, a.w, na[k]);
                dr[k] = fmaf(a.x, r.x, dr[k]);
                dr[k] = fmaf(a.y, r.y, dr[k]);
                dr[k] = fmaf(a.z, r.z, dr[k]);
                dr[k] = fmaf(a.w, r.w, dr[k]);
                nr[k] = fmaf(r.x, r.x, nr[k]);
                nr[k] = fmaf(r.y, r.y, nr[k]);
                nr[k] = fmaf(r.z, r.z, nr[k]);
                nr[k] = fmaf(r.w, r.w, nr[k]);
                dd[k] = fmaf(a.x, d.x, dd[k]);
                dd[k] = fmaf(a.y, d.y, dd[k]);
                dd[k] = fmaf(a.z, d.z, dd[k]);
                dd[k] = fmaf(a.w, d.w, dd[k]);
                nd[k] = fmaf(d.x, d.x, nd[k]);
                nd[k] = fmaf(d.y, d.y, nd[k]);
                nd[k] = fmaf(d.z, d.z, nd[k]);
                nd[k] = fmaf(d.w, d.w, nd[k]);
            }
        }
    }

    // Warp reductions + writes.
#pragma unroll
    for (int k = 0; k < TPW; k++) {
        if (!(am >> k & 1u)) continue;
        float sna = na[k], sdr = dr[k], snr = nr[k], sdd = dd[k], snd = nd[k];
#pragma unroll
        for (int off = 16; off > 0; off >>= 1) {
            sna += __shfl_xor_sync(0xFFFFFFFFu, sna, off);
            sdr += __shfl_xor_sync(0xFFFFFFFFu, sdr, off);
            snr += __shfl_xor_sync(0xFFFFFFFFu, snr, off);
            sdd += __shfl_xor_sync(0xFFFFFFFFu, sdd, off);
            snd += __shfl_xor_sync(0xFFFFFFFFu, snd, off);
        }
        if (lane == 0) {
            const int t = t0 + k;
            const float norm_a = fmaxf(sqrtf(sna), EPS);
            out_right[t] = (rm >> k & 1u)
                ? sdr / (norm_a * fmaxf(sqrtf(snr), EPS)) : -1.0f;
            out_down[t]  = (dm >> k & 1u)
                ? sdd / (norm_a * fmaxf(sqrtf(snd), EPS)) : -1.0f;
        }
    }
}

extern "C" void kernel_launch(void* const* d_in, const int* in_sizes, int n_in,
                              void* d_out, int out_size) {
    const float* x = (const float*)d_in[0];
    float* out       = (float*)d_out;
    float* out_right = out;
    float* out_down  = out + TOTAL;

    simdiff_l1<<<MAIN_BLOCKS + TAIL_BLOCKS, THREADS>>>(x, out_right, out_down);
}